// round 6
// baseline (speedup 1.0000x reference)
#include <cuda_runtime.h>
#include <cstdint>

// DynamicRouting (R5): mma.sync tf32 GEMM + Gram routing, 512 threads,
// con stored [px][g*68+fo] for float4 epilogue reads.

namespace {
constexpr int Gn   = 8;
constexpr int FIn  = 64;
constexpr int FOn  = 64;
constexpr int HWn  = 4096;
constexpr int Bn   = 16;
constexpr int PXT  = 64;
constexpr int THREADS = 512;        // 16 warps

constexpr int CGs = 68;             // con per-group stride (words)
constexpr int CPs = 548;            // con per-px row stride (8*68+4, 16B-aligned)
constexpr int SXs = 72;             // X [fi][px]
constexpr int SWs = 68;             // W [fo][fi]

constexpr int CONo = 0;                       // 64*548 = 35072 words
constexpr int X0o  = CONo + PXT * CPs;        // 35072
constexpr int X1o  = X0o + FIn * SXs;         // +4608
constexpr int W0o  = X1o + FIn * SXs;         // +4608
constexpr int W1o  = W0o + FOn * SWs;         // +4352
constexpr int ALPo = W1o + FOn * SWs;         // +4352 -> 52992
constexpr int SMEM_WORDS = ALPo + Gn * PXT;   // +512 -> 53504
constexpr int SMEM_BYTES = SMEM_WORDS * 4;    // 214016 B
}

__device__ __forceinline__ uint32_t cvt_tf32(float f) {
    uint32_t r;
    asm("cvt.rna.tf32.f32 %0, %1;" : "=r"(r) : "f"(f));
    return r;
}

__device__ __forceinline__ void mma_tf32(float c[4],
                                         uint32_t a0, uint32_t a1,
                                         uint32_t a2, uint32_t a3,
                                         uint32_t b0, uint32_t b1) {
    asm volatile(
        "mma.sync.aligned.m16n8k8.row.col.f32.tf32.tf32.f32 "
        "{%0,%1,%2,%3}, {%4,%5,%6,%7}, {%8,%9}, {%0,%1,%2,%3};"
        : "+f"(c[0]), "+f"(c[1]), "+f"(c[2]), "+f"(c[3])
        : "r"(a0), "r"(a1), "r"(a2), "r"(a3), "r"(b0), "r"(b1));
}

__device__ __forceinline__ float sigmoidf_(float v) {
    return 1.f / (1.f + __expf(-v));
}

__device__ __forceinline__ int pidx(int a, int b) {
    int lo = a < b ? a : b, hi = a < b ? b : a;
    return lo * 8 - lo * (lo - 1) / 2 + (hi - lo);
}

__global__ void __launch_bounds__(THREADS, 1)
dynrout_mma_kernel(const float* __restrict__ x,
                   const float* __restrict__ w,
                   const float* __restrict__ bias,
                   float* __restrict__ out)
{
    extern __shared__ uint32_t smu[];
    float* smf = reinterpret_cast<float*>(smu);

    const int t    = threadIdx.x;
    const int wid  = t >> 5;
    const int lane = t & 31;
    const int gid  = lane >> 2;
    const int tid4 = lane & 3;

    const int cta = blockIdx.x;
    const int bi  = cta >> 6;
    const int p0  = (cta & 63) * PXT;

    const int pxb = (wid & 3) * 16;     // px quarter
    const int fob = (wid >> 2) * 16;    // fo quarter

    // ---------------- gmem prefetch (regs, double-buffered SMEM) -------------
    float4 rx[2], rw[2];
    auto load_regs = [&](int g) {
        const float* xg = x + ((size_t)bi * (Gn * FIn) + g * FIn) * HWn + p0;
        const float* wg = w + (size_t)g * FOn * FIn;
        #pragma unroll
        for (int k = 0; k < 2; k++) {
            int q  = t + k * THREADS;   // 0..1023
            int r0 = q >> 4;
            int c4 = q & 15;
            rx[k] = *reinterpret_cast<const float4*>(xg + (size_t)r0 * HWn + c4 * 4);
            rw[k] = *reinterpret_cast<const float4*>(wg + r0 * FIn + c4 * 4);
        }
    };
    auto store_regs = [&](int buf) {
        const int xo = buf ? X1o : X0o;
        const int wo = buf ? W1o : W0o;
        #pragma unroll
        for (int k = 0; k < 2; k++) {
            int q  = t + k * THREADS;
            int r0 = q >> 4;
            int c4 = q & 15;
            uint4 xv = make_uint4(cvt_tf32(rx[k].x), cvt_tf32(rx[k].y),
                                  cvt_tf32(rx[k].z), cvt_tf32(rx[k].w));
            uint4 wv = make_uint4(cvt_tf32(rw[k].x), cvt_tf32(rw[k].y),
                                  cvt_tf32(rw[k].z), cvt_tf32(rw[k].w));
            *reinterpret_cast<uint4*>(&smu[xo + r0 * SXs + c4 * 4]) = xv;
            *reinterpret_cast<uint4*>(&smu[wo + r0 * SWs + c4 * 4]) = wv;
        }
    };

    // ---------------- GEMM over 8 groups -------------------------------------
    load_regs(0);
    store_regs(0);
    __syncthreads();

    for (int g = 0; g < Gn; g++) {
        if (g + 1 < Gn) load_regs(g + 1);

        const int xo = (g & 1) ? X1o : X0o;
        const int wo = (g & 1) ? W1o : W0o;

        float acc[2][4];
        #pragma unroll
        for (int n = 0; n < 2; n++)
            #pragma unroll
            for (int j = 0; j < 4; j++) acc[n][j] = 0.f;

        #pragma unroll
        for (int s = 0; s < 8; s++) {
            const int fi0 = s * 8;
            uint32_t a0 = smu[xo + (fi0 + tid4)     * SXs + pxb + gid];
            uint32_t a1 = smu[xo + (fi0 + tid4)     * SXs + pxb + gid + 8];
            uint32_t a2 = smu[xo + (fi0 + 4 + tid4) * SXs + pxb + gid];
            uint32_t a3 = smu[xo + (fi0 + 4 + tid4) * SXs + pxb + gid + 8];
            #pragma unroll
            for (int n = 0; n < 2; n++) {
                int fo = fob + n * 8 + gid;
                uint32_t b0 = smu[wo + fo * SWs + fi0 + tid4];
                uint32_t b1 = smu[wo + fo * SWs + fi0 + 4 + tid4];
                mma_tf32(acc[n], a0, a1, a2, a3, b0, b1);
            }
        }

        // con[px][g*68+fo]: fo-adjacent pairs -> STS.64
        #pragma unroll
        for (int n = 0; n < 2; n++) {
            int fo  = fob + n * 8 + 2 * tid4;
            int c0  = CONo + (pxb + gid)     * CPs + g * CGs + fo;
            int c1  = CONo + (pxb + gid + 8) * CPs + g * CGs + fo;
            *reinterpret_cast<float2*>(&smf[c0]) = make_float2(acc[n][0], acc[n][1]);
            *reinterpret_cast<float2*>(&smf[c1]) = make_float2(acc[n][2], acc[n][3]);
        }

        if (g + 1 < Gn) store_regs((g + 1) & 1);
        __syncthreads();
    }

    // ---------------- Gram pass (8 threads per px, fo split 8-way) -----------
    {
        const int px  = t >> 3;     // 0..63
        const int foc = t & 7;      // fo chunk: fo = foc*8 + i
        float acc[36];
        #pragma unroll
        for (int p = 0; p < 36; p++) acc[p] = 0.f;

        #pragma unroll
        for (int h = 0; h < 2; h++) {        // two fo-halves of 4
            float cg[Gn][4];
            #pragma unroll
            for (int j = 0; j < Gn; j++) {   // staggered group -> conflict-free
                int g = (j + foc) & 7;
                float4 v = *reinterpret_cast<const float4*>(
                    &smf[CONo + px * CPs + g * CGs + foc * 8 + h * 4]);
                cg[g][0] = v.x; cg[g][1] = v.y; cg[g][2] = v.z; cg[g][3] = v.w;
            }
            int p = 0;
            #pragma unroll
            for (int a = 0; a < Gn; a++)
                #pragma unroll
                for (int b = a; b < Gn; b++) {
                    float s = acc[p];
                    #pragma unroll
                    for (int i = 0; i < 4; i++) s += cg[a][i] * cg[b][i];
                    acc[p++] = s;
                }
        }
        #pragma unroll
        for (int p = 0; p < 36; p++) {
            acc[p] += __shfl_xor_sync(0xFFFFFFFFu, acc[p], 1);
            acc[p] += __shfl_xor_sync(0xFFFFFFFFu, acc[p], 2);
            acc[p] += __shfl_xor_sync(0xFFFFFFFFu, acc[p], 4);
        }

        // routing on 8x8 Gram (redundant across octet; foc==0 stores alpha)
        float beta[Gn], alpha[Gn];
        #pragma unroll
        for (int g = 0; g < Gn; g++) {
            float s = 0.f;
            #pragma unroll
            for (int g2 = 0; g2 < Gn; g2++) s += acc[pidx(g2, g)];
            beta[g] = 0.5f * s;
        }
        #pragma unroll
        for (int g = 0; g < Gn; g++) alpha[g] = sigmoidf_(beta[g]);
        #pragma unroll
        for (int g = 0; g < Gn; g++) {
            float s = 0.f;
            #pragma unroll
            for (int g2 = 0; g2 < Gn; g2++) s += alpha[g2] * acc[pidx(g2, g)];
            beta[g] += s;
        }
        if (foc == 0) {
            #pragma unroll
            for (int g = 0; g < Gn; g++)
                smf[ALPo + g * PXT + px] = sigmoidf_(beta[g]);
        }
    }
    __syncthreads();

    // ---------------- final pass: out = sum_g alpha*con + bias ---------------
    {
        const int px  = t & 63;
        const int foc = t >> 6;     // 0..7
        float al[Gn];
        #pragma unroll
        for (int g = 0; g < Gn; g++) al[g] = smf[ALPo + g * PXT + px];

        float s[8];
        #pragma unroll
        for (int i = 0; i < 8; i++) s[i] = 0.f;

        #pragma unroll
        for (int g = 0; g < Gn; g++) {
            const float4* cp = reinterpret_cast<const float4*>(
                &smf[CONo + px * CPs + g * CGs + foc * 8]);
            float4 v0 = cp[0];
            float4 v1 = cp[1];
            s[0] += al[g] * v0.x; s[1] += al[g] * v0.y;
            s[2] += al[g] * v0.z; s[3] += al[g] * v0.w;
            s[4] += al[g] * v1.x; s[5] += al[g] * v1.y;
            s[6] += al[g] * v1.z; s[7] += al[g] * v1.w;
        }

        float* ob = out + (size_t)bi * FOn * HWn + p0;
        #pragma unroll
        for (int i = 0; i < 8; i++) {
            int fo = foc * 8 + i;
            ob[(size_t)fo * HWn + px] = s[i] + __ldg(&bias[fo]);
        }
    }
}

extern "C" void kernel_launch(void* const* d_in, const int* in_sizes, int n_in,
                              void* d_out, int out_size)
{
    const float* x = nullptr;
    const float* w = nullptr;
    const float* b = nullptr;
    for (int i = 0; i < n_in; i++) {
        if (in_sizes[i] == Bn * Gn * FIn * HWn)      x = (const float*)d_in[i];
        else if (in_sizes[i] == Gn * FOn * FIn)      w = (const float*)d_in[i];
        else if (in_sizes[i] == FOn)                 b = (const float*)d_in[i];
    }
    float* out = (float*)d_out;

    static bool attr_set = false;
    if (!attr_set) {
        cudaFuncSetAttribute(dynrout_mma_kernel,
                             cudaFuncAttributeMaxDynamicSharedMemorySize, SMEM_BYTES);
        attr_set = true;
    }

    const int n_ctas = (Bn * HWn) / PXT;   // 1024
    dynrout_mma_kernel<<<n_ctas, THREADS, SMEM_BYTES>>>(x, w, b, out);
}

// round 7
// speedup vs baseline: 2.1218x; 2.1218x over previous
#include <cuda_runtime.h>
#include <cstdint>

// DynamicRouting (R6): R4 structure (256 thr, mma.sync tf32, Gram routing)
// with PXT=32 and 96 KB SMEM -> 2 CTAs/SM for latency hiding.

namespace {
constexpr int Gn   = 8;
constexpr int FIn  = 64;
constexpr int FOn  = 64;
constexpr int HWn  = 4096;
constexpr int Bn   = 16;
constexpr int PXT  = 32;            // pixels per CTA
constexpr int THREADS = 256;        // 8 warps

constexpr int SCs = 33;             // con [g*64+fo][px]
constexpr int SXs = 40;             // X [fi][px] : bank = (8*fi + px) % 32
constexpr int SWs = 68;             // W [fo][fi] : bank = (4*fo + fi) % 32

constexpr int CONo = 0;                          // 512*33 = 16896 words
constexpr int Xo   = CONo + Gn * FOn * SCs;      // 16896
constexpr int Wo   = Xo + FIn * SXs;             // +2560 -> 19456
constexpr int ALPo = Wo + FOn * SWs;             // +4352 -> 23808
constexpr int SMEM_WORDS = ALPo + Gn * PXT;      // +256  -> 24064
constexpr int SMEM_BYTES = SMEM_WORDS * 4;       // 96256 B  (2 CTAs/SM)
}

__device__ __forceinline__ uint32_t cvt_tf32(float f) {
    uint32_t r;
    asm("cvt.rna.tf32.f32 %0, %1;" : "=r"(r) : "f"(f));
    return r;
}

__device__ __forceinline__ void mma_tf32(float c[4],
                                         uint32_t a0, uint32_t a1,
                                         uint32_t a2, uint32_t a3,
                                         uint32_t b0, uint32_t b1) {
    asm volatile(
        "mma.sync.aligned.m16n8k8.row.col.f32.tf32.tf32.f32 "
        "{%0,%1,%2,%3}, {%4,%5,%6,%7}, {%8,%9}, {%0,%1,%2,%3};"
        : "+f"(c[0]), "+f"(c[1]), "+f"(c[2]), "+f"(c[3])
        : "r"(a0), "r"(a1), "r"(a2), "r"(a3), "r"(b0), "r"(b1));
}

__device__ __forceinline__ float sigmoidf_(float v) {
    return 1.f / (1.f + __expf(-v));
}

__device__ __forceinline__ int pidx(int a, int b) {
    int lo = a < b ? a : b, hi = a < b ? b : a;
    return lo * 8 - lo * (lo - 1) / 2 + (hi - lo);
}

__global__ void __launch_bounds__(THREADS, 2)
dynrout_mma_kernel(const float* __restrict__ x,
                   const float* __restrict__ w,
                   const float* __restrict__ bias,
                   float* __restrict__ out)
{
    extern __shared__ uint32_t smu[];
    float* smf = reinterpret_cast<float*>(smu);

    const int t    = threadIdx.x;
    const int wid  = t >> 5;
    const int lane = t & 31;
    const int gid  = lane >> 2;
    const int tid4 = lane & 3;

    const int cta = blockIdx.x;
    const int bi  = cta >> 7;           // 128 px-tiles per image
    const int p0  = (cta & 127) * PXT;

    // warp tile: 16 px x 16 fo  (2 px-halves x 4 fo-quarters)
    const int pxb = (wid & 1) * 16;
    const int fob = (wid >> 1) * 16;

    // ---------------- gmem prefetch into registers ---------------------------
    float4 rx[2], rw[4];
    auto load_regs = [&](int g) {
        const float* xg = x + ((size_t)bi * (Gn * FIn) + g * FIn) * HWn + p0;
        const float* wg = w + (size_t)g * FOn * FIn;
        #pragma unroll
        for (int k = 0; k < 2; k++) {       // X: 64 fi x 32 px = 512 float4
            int q  = t + k * THREADS;       // 0..511
            int fi = q >> 3;
            int c4 = q & 7;
            rx[k] = *reinterpret_cast<const float4*>(xg + (size_t)fi * HWn + c4 * 4);
        }
        #pragma unroll
        for (int k = 0; k < 4; k++) {       // W: 64 fo x 64 fi = 1024 float4
            int q  = t + k * THREADS;
            int fo = q >> 4;
            int c4 = q & 15;
            rw[k] = *reinterpret_cast<const float4*>(wg + fo * FIn + c4 * 4);
        }
    };
    auto store_regs = [&]() {
        #pragma unroll
        for (int k = 0; k < 2; k++) {
            int q  = t + k * THREADS;
            int fi = q >> 3;
            int c4 = q & 7;
            uint4 xv = make_uint4(cvt_tf32(rx[k].x), cvt_tf32(rx[k].y),
                                  cvt_tf32(rx[k].z), cvt_tf32(rx[k].w));
            *reinterpret_cast<uint4*>(&smu[Xo + fi * SXs + c4 * 4]) = xv;
        }
        #pragma unroll
        for (int k = 0; k < 4; k++) {
            int q  = t + k * THREADS;
            int fo = q >> 4;
            int c4 = q & 15;
            uint4 wv = make_uint4(cvt_tf32(rw[k].x), cvt_tf32(rw[k].y),
                                  cvt_tf32(rw[k].z), cvt_tf32(rw[k].w));
            *reinterpret_cast<uint4*>(&smu[Wo + fo * SWs + c4 * 4]) = wv;
        }
    };

    // ---------------- GEMM over 8 groups (reg double-buffer, 1 SMEM buf) -----
    load_regs(0);
    store_regs();
    __syncthreads();

    for (int g = 0; g < Gn; g++) {
        if (g + 1 < Gn) load_regs(g + 1);   // gmem -> regs, overlaps MMA

        float acc[2][4];
        #pragma unroll
        for (int n = 0; n < 2; n++)
            #pragma unroll
            for (int j = 0; j < 4; j++) acc[n][j] = 0.f;

        #pragma unroll
        for (int s = 0; s < 8; s++) {
            const int fi0 = s * 8;
            uint32_t a0 = smu[Xo + (fi0 + tid4)     * SXs + pxb + gid];
            uint32_t a1 = smu[Xo + (fi0 + tid4)     * SXs + pxb + gid + 8];
            uint32_t a2 = smu[Xo + (fi0 + 4 + tid4) * SXs + pxb + gid];
            uint32_t a3 = smu[Xo + (fi0 + 4 + tid4) * SXs + pxb + gid + 8];
            #pragma unroll
            for (int n = 0; n < 2; n++) {
                int fo = fob + n * 8 + gid;
                uint32_t b0 = smu[Wo + fo * SWs + fi0 + tid4];
                uint32_t b1 = smu[Wo + fo * SWs + fi0 + 4 + tid4];
                mma_tf32(acc[n], a0, a1, a2, a3, b0, b1);
            }
        }

        // store con[g][fo][px]
        #pragma unroll
        for (int n = 0; n < 2; n++) {
            int fo = fob + n * 8 + 2 * tid4;
            int cb = CONo + (g * FOn + fo) * SCs;
            smf[cb         + pxb + gid]     = acc[n][0];
            smf[cb + SCs   + pxb + gid]     = acc[n][1];
            smf[cb         + pxb + gid + 8] = acc[n][2];
            smf[cb + SCs   + pxb + gid + 8] = acc[n][3];
        }

        __syncthreads();                    // con stores + SMEM reads done
        if (g + 1 < Gn) {
            store_regs();                   // overwrite single buffer
            __syncthreads();
        }
    }

    // ---------------- Gram pass (8 threads per px) ---------------------------
    {
        const int px  = t >> 3;             // 0..31
        const int foc = t & 7;              // 8-fo chunk
        float acc[36];
        #pragma unroll
        for (int p = 0; p < 36; p++) acc[p] = 0.f;

        #pragma unroll
        for (int i = 0; i < 8; i++) {
            int fo = foc * 8 + ((i + foc) & 7);   // staggered -> few conflicts
            float cg[Gn];
            #pragma unroll
            for (int g = 0; g < Gn; g++)
                cg[g] = smf[CONo + (g * FOn + fo) * SCs + px];
            int p = 0;
            #pragma unroll
            for (int a = 0; a < Gn; a++)
                #pragma unroll
                for (int b = a; b < Gn; b++)
                    acc[p++] += cg[a] * cg[b];
        }
        #pragma unroll
        for (int p = 0; p < 36; p++) {
            acc[p] += __shfl_xor_sync(0xFFFFFFFFu, acc[p], 1);
            acc[p] += __shfl_xor_sync(0xFFFFFFFFu, acc[p], 2);
            acc[p] += __shfl_xor_sync(0xFFFFFFFFu, acc[p], 4);
        }

        // routing on 8x8 Gram (redundant across octet; foc==0 stores alpha)
        float beta[Gn], alpha[Gn];
        #pragma unroll
        for (int g = 0; g < Gn; g++) {
            float s = 0.f;
            #pragma unroll
            for (int g2 = 0; g2 < Gn; g2++) s += acc[pidx(g2, g)];
            beta[g] = 0.5f * s;
        }
        #pragma unroll
        for (int g = 0; g < Gn; g++) alpha[g] = sigmoidf_(beta[g]);
        #pragma unroll
        for (int g = 0; g < Gn; g++) {
            float s = 0.f;
            #pragma unroll
            for (int g2 = 0; g2 < Gn; g2++) s += alpha[g2] * acc[pidx(g2, g)];
            beta[g] += s;
        }
        if (foc == 0) {
            #pragma unroll
            for (int g = 0; g < Gn; g++)
                smf[ALPo + g * PXT + px] = sigmoidf_(beta[g]);
        }
    }
    __syncthreads();

    // ---------------- final pass: out = sum_g alpha*con + bias ---------------
    {
        const int px  = t & 31;
        const int foc = t >> 5;             // 0..7
        float al[Gn];
        #pragma unroll
        for (int g = 0; g < Gn; g++) al[g] = smf[ALPo + g * PXT + px];

        float s[8];
        #pragma unroll
        for (int i = 0; i < 8; i++) s[i] = 0.f;

        #pragma unroll
        for (int g = 0; g < Gn; g++)
            #pragma unroll
            for (int i = 0; i < 8; i++)
                s[i] += al[g] * smf[CONo + (g * FOn + foc * 8 + i) * SCs + px];

        float* ob = out + (size_t)bi * FOn * HWn + p0;
        #pragma unroll
        for (int i = 0; i < 8; i++) {
            int fo = foc * 8 + i;
            ob[(size_t)fo * HWn + px] = s[i] + __ldg(&bias[fo]);
        }
    }
}

extern "C" void kernel_launch(void* const* d_in, const int* in_sizes, int n_in,
                              void* d_out, int out_size)
{
    const float* x = nullptr;
    const float* w = nullptr;
    const float* b = nullptr;
    for (int i = 0; i < n_in; i++) {
        if (in_sizes[i] == Bn * Gn * FIn * HWn)      x = (const float*)d_in[i];
        else if (in_sizes[i] == Gn * FOn * FIn)      w = (const float*)d_in[i];
        else if (in_sizes[i] == FOn)                 b = (const float*)d_in[i];
    }
    float* out = (float*)d_out;

    static bool attr_set = false;
    if (!attr_set) {
        cudaFuncSetAttribute(dynrout_mma_kernel,
                             cudaFuncAttributeMaxDynamicSharedMemorySize, SMEM_BYTES);
        attr_set = true;
    }

    const int n_ctas = (Bn * HWn) / PXT;   // 2048
    dynrout_mma_kernel<<<n_ctas, THREADS, SMEM_BYTES>>>(x, w, b, out);
}